// round 3
// baseline (speedup 1.0000x reference)
#include <cuda_runtime.h>
#include <cstdint>

#define BATCH 64
#define NTOK  65536            // 256*256
#define KSEL  16384
#define TOTAL (BATCH * NTOK)
#define NGRP  (TOTAL / 4)      // 1,048,576 groups of 4 tokens
#define CANDCAP 4096           // per-batch candidate capacity (global)
#define CANDB   256            // per-block candidate capacity (smem)

// ---- device scratch (device globals; no allocations) ----
__device__ float4   g_d[NGRP];             // 16 MB: per-token d values
__device__ uint32_t g_cand[BATCH * CANDCAP];
__device__ uint32_t g_nc[BATCH];           // candidate counts  (zero-init, reset by finalize)
__device__ uint32_t g_c2[BATCH];           // counts >= P2      (zero-init, reset by finalize)
__device__ uint32_t g_of[BATCH];           // overflow flags    (zero-init, reset by finalize)
__device__ uint32_t g_T[BATCH];            // threshold bit pattern
__device__ uint32_t g_req[BATCH];          // #(==T) to include
__device__ uint32_t g_eqcnt[BATCH];        // runtime tie counter
__device__ double   g_acc;                 // loss accumulator
__device__ unsigned g_doneC;               // finalize ticket

#define P1F 0.73f
#define P2F 0.77f

// softplus pieces: sp(d) = c + max(d,0), c = ln(1+e^{-|d|})
__device__ __forceinline__ float sp_c(float d) {
    return __logf(1.0f + __expf(-fabsf(d)));
}

// ============================================================================
// Kernel A: single full-data sweep.
//  - d = (z0+g0)-(z1+g1) -> g_d
//  - S0 = sum over ALL tokens of min(softplus(d),100) -> g_acc
//  - select window: count u>=P2 per batch; gather P1<=u<P2 candidates
// Block = 256 thr, 512 groups (2048 tokens) = exactly 1/32 of one batch.
// ============================================================================
__global__ __launch_bounds__(256) void sweep_kernel(const float4* __restrict__ zs4,
                                                    const uint4*  __restrict__ sm4,
                                                    const float4* __restrict__ gn4) {
    __shared__ uint32_t scand[CANDB];
    __shared__ uint32_t sNc, sBase;
    __shared__ uint32_t sc2[8];
    __shared__ double   wpart[8];

    const int t    = threadIdx.x;
    const int lane = t & 31;
    const int w    = t >> 5;
    const int b    = blockIdx.x >> 5;              // 32 blocks per batch
    const int blockBase = blockIdx.x * 512;        // group base

    if (t == 0) sNc = 0u;
    __syncthreads();

    const uint32_t P1 = __float_as_uint(P1F);
    const uint32_t P2 = __float_as_uint(P2F);

    double acc = 0.0;
    uint32_t cnt2 = 0;

    #pragma unroll
    for (int j = 0; j < 2; j++) {
        const int g = blockBase + w * 64 + j * 32 + lane;
        uint4  u  = sm4[g];
        float4 za = __ldcs(&zs4[2 * g]);
        float4 zb = __ldcs(&zs4[2 * g + 1]);
        float4 ga = __ldcs(&gn4[2 * g]);
        float4 gb = __ldcs(&gn4[2 * g + 1]);
        float4 dv;
        dv.x = (za.x + ga.x) - (za.y + ga.y);
        dv.y = (za.z + ga.z) - (za.w + ga.w);
        dv.z = (zb.x + gb.x) - (zb.y + gb.y);
        dv.w = (zb.z + gb.z) - (zb.w + gb.w);
        g_d[g] = dv;

        #pragma unroll
        for (int c = 0; c < 4; c++) {
            float d = (c == 0) ? dv.x : (c == 1) ? dv.y : (c == 2) ? dv.z : dv.w;
            acc += (double)fminf(sp_c(d) + fmaxf(d, 0.0f), 100.0f);
            uint32_t uu = (c == 0) ? u.x : (c == 1) ? u.y : (c == 2) ? u.z : u.w;
            cnt2 += (uu >= P2);
            bool isC = (uu >= P1) && (uu < P2);
            unsigned m = __ballot_sync(0xFFFFFFFFu, isC);
            if (m) {
                int leader = __ffs(m) - 1;
                uint32_t base = 0;
                if (lane == leader) base = atomicAdd(&sNc, (uint32_t)__popc(m));
                base = __shfl_sync(0xFFFFFFFFu, base, leader);
                if (isC) {
                    uint32_t idx = base + __popc(m & ((1u << lane) - 1u));
                    if (idx < CANDB) scand[idx] = uu;
                }
            }
        }
    }

    // warp-reduce cnt2 and acc
    #pragma unroll
    for (int off = 16; off > 0; off >>= 1) {
        cnt2 += __shfl_down_sync(0xFFFFFFFFu, cnt2, off);
        acc  += __shfl_down_sync(0xFFFFFFFFu, acc,  off);
    }
    if (lane == 0) { sc2[w] = cnt2; wpart[w] = acc; }
    __syncthreads();

    if (t == 0) {
        uint32_t tot2 = 0; double bsum = 0.0;
        #pragma unroll
        for (int i = 0; i < 8; i++) { tot2 += sc2[i]; bsum += wpart[i]; }
        atomicAdd(&g_c2[b], tot2);
        atomicAdd(&g_acc, bsum);
        uint32_t n = sNc;
        if (n > CANDB) { g_of[b] = 1u; n = CANDB; }
        uint32_t base = atomicAdd(&g_nc[b], n);
        if (base + n > CANDCAP) g_of[b] = 1u;
        sBase = base;
    }
    __syncthreads();

    uint32_t n = (sNc > CANDB) ? CANDB : sNc;
    uint32_t base = sBase;
    for (uint32_t i = t; i < n; i += 256)
        if (base + i < CANDCAP) g_cand[b * CANDCAP + base + i] = scand[i];
}

// ============================================================================
// Kernel B: per-batch exact threshold. 64 CTAs x 512 threads.
// ============================================================================
__device__ __forceinline__ uint32_t suffix_excl_512(uint32_t v, uint32_t* wsum) {
    const int t = threadIdx.x, lane = t & 31, w = t >> 5;
    uint32_t s = v;
    #pragma unroll
    for (int off = 1; off < 32; off <<= 1) {
        uint32_t o = __shfl_down_sync(0xFFFFFFFFu, s, off);
        if (lane + off < 32) s += o;
    }
    if (lane == 0) wsum[w] = s;
    __syncthreads();
    if (t < 32) {
        uint32_t x  = (t < 16) ? wsum[t] : 0u;
        uint32_t sx = x;
        #pragma unroll
        for (int off = 1; off < 16; off <<= 1) {
            uint32_t o = __shfl_down_sync(0xFFFFFFFFu, sx, off);
            if (t + off < 16) sx += o;
        }
        if (t < 16) wsum[t] = sx - x;
    }
    __syncthreads();
    return wsum[w] + (s - v);
}

__global__ __launch_bounds__(512) void thresh_kernel(const float* __restrict__ smap) {
    __shared__ uint32_t hist[2048];
    __shared__ uint32_t wsum[32];
    __shared__ uint32_t sBin, sK;

    const int b = blockIdx.x;
    const int t = threadIdx.x;

    const uint32_t nc = g_nc[b];
    const uint32_t c2 = g_c2[b];
    const bool miss = (g_of[b] != 0u) || (c2 >= KSEL) || (c2 + nc < KSEL) || (nc > CANDCAP);

    const uint32_t* __restrict__ cand = g_cand + b * CANDCAP;
    const uint32_t* __restrict__ full =
        reinterpret_cast<const uint32_t*>(smap) + (size_t)b * NTOK;

    uint32_t Kcur = miss ? (uint32_t)KSEL : (uint32_t)KSEL - c2;
    uint32_t prefixVal = 0;

    const int shifts[3] = {21, 10, 0};
    const int nbitsA[3] = {11, 11, 10};

    #pragma unroll
    for (int r = 0; r < 3; r++) {
        const int shift = shifts[r];
        const int nbits = nbitsA[r];
        const int nbins = 1 << nbits;
        const int hishift = shift + nbits;          // 32 on round 0 (unused)

        for (int i = t; i < nbins; i += 512) hist[i] = 0u;
        __syncthreads();

        if (!miss) {
            for (uint32_t i = t; i < nc; i += 512) {
                uint32_t u = cand[i];
                bool match = (r == 0) || ((u >> hishift) == prefixVal);
                if (match) atomicAdd(&hist[(u >> shift) & (uint32_t)(nbins - 1)], 1u);
            }
        } else {
            for (int i = t; i < NTOK; i += 512) {
                uint32_t u = full[i];
                bool match = (r == 0) || ((u >> hishift) == prefixVal);
                if (match) atomicAdd(&hist[(u >> shift) & (uint32_t)(nbins - 1)], 1u);
            }
        }
        __syncthreads();

        const int bpt  = nbins >> 9;                // 4 or 2
        const int base = t * bpt;
        uint32_t p = 0;
        #pragma unroll
        for (int j = 0; j < 4; j++)
            if (j < bpt) p += hist[base + j];
        uint32_t sfx = suffix_excl_512(p, wsum);    // bins above my chunk
        for (int j = bpt - 1; j >= 0; j--) {
            uint32_t h = hist[base + j];
            uint32_t s_incl = sfx + h;
            if (sfx < Kcur && s_incl >= Kcur) { sBin = (uint32_t)(base + j); sK = Kcur - sfx; }
            sfx = s_incl;
        }
        __syncthreads();
        prefixVal = (prefixVal << nbits) | sBin;
        Kcur = sK;
        __syncthreads();
    }

    if (t == 0) { g_T[b] = prefixVal; g_req[b] = Kcur; }
}

// ============================================================================
// Kernel C: selected-token correction (L2-hot) + finalize + scratch reset.
// corr = min(sp - d, 100) - min(sp, 100),  sp = c + max(d,0)
// Block = 256 thr, 1024 groups (4096 tokens) = 1/16 of one batch.
// ============================================================================
__global__ __launch_bounds__(256) void corr_kernel(const uint4* __restrict__ sm4,
                                                   float* __restrict__ out,
                                                   unsigned nblocks) {
    __shared__ double wpart[8];
    const int t    = threadIdx.x;
    const int lane = t & 31;
    const int w    = t >> 5;
    const int b    = blockIdx.x >> 4;               // 16 blocks per batch
    const int base = blockIdx.x * 1024;
    const uint32_t T = g_T[b];

    double acc = 0.0;
    #pragma unroll
    for (int j = 0; j < 4; j++) {
        const int g = base + w * 128 + j * 32 + lane;
        uint4  u  = sm4[g];
        float4 dv = g_d[g];
        #pragma unroll
        for (int c = 0; c < 4; c++) {
            uint32_t uu = (c == 0) ? u.x : (c == 1) ? u.y : (c == 2) ? u.z : u.w;
            float    d  = (c == 0) ? dv.x : (c == 1) ? dv.y : (c == 2) ? dv.z : dv.w;
            bool sel;
            if (uu > T)       sel = true;
            else if (uu == T) sel = (atomicAdd(&g_eqcnt[b], 1u) < g_req[b]);  // rare
            else              sel = false;
            if (sel) {
                float sp = sp_c(d) + fmaxf(d, 0.0f);
                acc += (double)(fminf(sp - d, 100.0f) - fminf(sp, 100.0f));
            }
        }
    }

    #pragma unroll
    for (int off = 16; off > 0; off >>= 1)
        acc += __shfl_down_sync(0xFFFFFFFFu, acc, off);
    if (lane == 0) wpart[w] = acc;
    __syncthreads();

    if (t == 0) {
        double bsum = 0.0;
        #pragma unroll
        for (int i = 0; i < 8; i++) bsum += wpart[i];
        atomicAdd(&g_acc, bsum);
        __threadfence();
        unsigned ticket = atomicAdd(&g_doneC, 1u);
        if (ticket == nblocks - 1) {                 // last block: finalize + reset
            __threadfence();
            out[0] = (float)atomicAdd(&g_acc, 0.0);
            #pragma unroll 4
            for (int i = 0; i < BATCH; i++) {
                g_c2[i] = 0u; g_nc[i] = 0u; g_of[i] = 0u; g_eqcnt[i] = 0u;
            }
            g_acc = 0.0;
            __threadfence();
            g_doneC = 0u;
        }
    }
}

extern "C" void kernel_launch(void* const* d_in, const int* in_sizes, int n_in,
                              void* d_out, int out_size) {
    const float* scores = (const float*)d_in[0];   // [B, N, 2]
    const float* smap   = (const float*)d_in[1];   // [B, 1, H, W] == [B, N]
    const float* gumb   = (const float*)d_in[2];   // [B, N, 2]
    float* out = (float*)d_out;

    sweep_kernel<<<2048, 256>>>((const float4*)scores, (const uint4*)smap,
                                (const float4*)gumb);
    thresh_kernel<<<BATCH, 512>>>(smap);
    corr_kernel<<<1024, 256>>>((const uint4*)smap, out, 1024u);
}

// round 4
// speedup vs baseline: 1.7863x; 1.7863x over previous
#include <cuda_runtime.h>
#include <cstdint>

#define BATCH 64
#define NTOK  65536            // 256*256
#define KSEL  16384
#define TOTAL (BATCH * NTOK)
#define NGRP  (TOTAL / 4)      // 1,048,576 groups of 4 tokens
#define CANDCAP 4096           // per-batch candidate capacity (global)
#define CANDB   384            // per-block candidate capacity (smem)

// ---- device scratch (device globals; no allocations) ----
__device__ uint32_t g_cand[BATCH * CANDCAP];
__device__ uint32_t g_nc[BATCH];     // candidate counts (zero-init; reset by finalize)
__device__ uint32_t g_c2[BATCH];     // counts >= P2     (zero-init; reset by finalize)
__device__ uint32_t g_of[BATCH];     // overflow flags   (zero-init; reset by finalize)
__device__ uint32_t g_T[BATCH];      // threshold bit pattern
__device__ uint32_t g_req[BATCH];    // #(==T) to include
__device__ uint32_t g_eqcnt[BATCH];  // runtime tie counter
__device__ double   g_acc;           // loss accumulator
__device__ unsigned g_done;          // finalize ticket

#define P1F 0.73f
#define P2F 0.77f

// ============================================================================
// Kernel 1: smap-only sweep (16 MB). Per batch: count u>=P2, gather window
// candidates P1<=u<P2. 1024 blocks (16 per batch) x 256 thr x 4 uint4/thread.
// Candidates ~4% of elements -> direct smem atomics are cheap; no ballots.
// ============================================================================
__global__ __launch_bounds__(256) void gather_kernel(const uint4* __restrict__ sm4) {
    __shared__ uint32_t scand[CANDB];
    __shared__ uint32_t sNc, sBase;
    __shared__ uint32_t sc2[8];

    const int t    = threadIdx.x;
    const int lane = t & 31;
    const int w    = t >> 5;
    const int b    = blockIdx.x >> 4;              // 16 blocks per batch
    const int blockBase = blockIdx.x * 1024;       // uint4-group base

    if (t == 0) sNc = 0u;
    __syncthreads();

    const uint32_t P1 = __float_as_uint(P1F);
    const uint32_t P2 = __float_as_uint(P2F);

    uint4 v[4];
    #pragma unroll
    for (int j = 0; j < 4; j++) v[j] = sm4[blockBase + j * 256 + t];

    uint32_t cnt2 = 0;
    #pragma unroll
    for (int j = 0; j < 4; j++) {
        #pragma unroll
        for (int c = 0; c < 4; c++) {
            uint32_t u = (c == 0) ? v[j].x : (c == 1) ? v[j].y : (c == 2) ? v[j].z : v[j].w;
            cnt2 += (u >= P2);
            if (u >= P1 && u < P2) {
                uint32_t idx = atomicAdd(&sNc, 1u);
                if (idx < CANDB) scand[idx] = u;
            }
        }
    }

    #pragma unroll
    for (int off = 16; off > 0; off >>= 1)
        cnt2 += __shfl_down_sync(0xFFFFFFFFu, cnt2, off);
    if (lane == 0) sc2[w] = cnt2;
    __syncthreads();

    if (t == 0) {
        uint32_t tot2 = 0;
        #pragma unroll
        for (int i = 0; i < 8; i++) tot2 += sc2[i];
        atomicAdd(&g_c2[b], tot2);
        uint32_t n = sNc;
        if (n > CANDB) { g_of[b] = 1u; n = CANDB; }
        uint32_t base = atomicAdd(&g_nc[b], n);
        if (base + n > CANDCAP) g_of[b] = 1u;
        sBase = base;
    }
    __syncthreads();

    uint32_t n = (sNc > CANDB) ? CANDB : sNc;
    uint32_t base = sBase;
    for (uint32_t i = t; i < n; i += 256)
        if (base + i < CANDCAP) g_cand[b * CANDCAP + base + i] = scand[i];
}

// ============================================================================
// Kernel 2: per-batch exact threshold among candidates (L2-hot).
// Full-radix fallback over smap on window miss (never taken at this input).
// ============================================================================
__device__ __forceinline__ uint32_t suffix_excl_512(uint32_t v, uint32_t* wsum) {
    const int t = threadIdx.x, lane = t & 31, w = t >> 5;
    uint32_t s = v;
    #pragma unroll
    for (int off = 1; off < 32; off <<= 1) {
        uint32_t o = __shfl_down_sync(0xFFFFFFFFu, s, off);
        if (lane + off < 32) s += o;
    }
    if (lane == 0) wsum[w] = s;
    __syncthreads();
    if (t < 32) {
        uint32_t x  = (t < 16) ? wsum[t] : 0u;
        uint32_t sx = x;
        #pragma unroll
        for (int off = 1; off < 16; off <<= 1) {
            uint32_t o = __shfl_down_sync(0xFFFFFFFFu, sx, off);
            if (t + off < 16) sx += o;
        }
        if (t < 16) wsum[t] = sx - x;
    }
    __syncthreads();
    return wsum[w] + (s - v);
}

__global__ __launch_bounds__(512) void thresh_kernel(const float* __restrict__ smap) {
    __shared__ uint32_t hist[2048];
    __shared__ uint32_t wsum[32];
    __shared__ uint32_t sBin, sK;

    const int b = blockIdx.x;
    const int t = threadIdx.x;

    const uint32_t nc = g_nc[b];
    const uint32_t c2 = g_c2[b];
    const bool miss = (g_of[b] != 0u) || (c2 >= KSEL) || (c2 + nc < KSEL) || (nc > CANDCAP);

    const uint32_t* __restrict__ cand = g_cand + b * CANDCAP;
    const uint32_t* __restrict__ full =
        reinterpret_cast<const uint32_t*>(smap) + (size_t)b * NTOK;

    uint32_t Kcur = miss ? (uint32_t)KSEL : (uint32_t)KSEL - c2;
    uint32_t prefixVal = 0;

    const int shifts[3] = {21, 10, 0};
    const int nbitsA[3] = {11, 11, 10};

    #pragma unroll
    for (int r = 0; r < 3; r++) {
        const int shift = shifts[r];
        const int nbits = nbitsA[r];
        const int nbins = 1 << nbits;
        const int hishift = shift + nbits;          // 32 on round 0 (unused)

        for (int i = t; i < nbins; i += 512) hist[i] = 0u;
        __syncthreads();

        if (!miss) {
            for (uint32_t i = t; i < nc; i += 512) {
                uint32_t u = cand[i];
                bool match = (r == 0) || ((u >> hishift) == prefixVal);
                if (match) atomicAdd(&hist[(u >> shift) & (uint32_t)(nbins - 1)], 1u);
            }
        } else {
            for (int i = t; i < NTOK; i += 512) {
                uint32_t u = full[i];
                bool match = (r == 0) || ((u >> hishift) == prefixVal);
                if (match) atomicAdd(&hist[(u >> shift) & (uint32_t)(nbins - 1)], 1u);
            }
        }
        __syncthreads();

        const int bpt  = nbins >> 9;                // 4 or 2
        const int base = t * bpt;
        uint32_t p = 0;
        #pragma unroll
        for (int j = 0; j < 4; j++)
            if (j < bpt) p += hist[base + j];
        uint32_t sfx = suffix_excl_512(p, wsum);
        for (int j = bpt - 1; j >= 0; j--) {
            uint32_t h = hist[base + j];
            uint32_t s_incl = sfx + h;
            if (sfx < Kcur && s_incl >= Kcur) { sBin = (uint32_t)(base + j); sK = Kcur - sfx; }
            sfx = s_incl;
        }
        __syncthreads();
        prefixVal = (prefixVal << nbits) | sBin;
        Kcur = sK;
        __syncthreads();
    }

    if (t == 0) { g_T[b] = prefixVal; g_req[b] = Kcur; }
}

// ============================================================================
// Kernel 3: loss sweep (67 MB scores+gumbel DRAM + 16 MB smap, L2-hot).
// term = min(c + max(d,0) - sel*d, 100), c = ln(1+e^{-|d|}).
// 1024 blocks x 256 thr x 4 groups/thread; all 20 LDG.128 issued up front.
// Per-thread fp32 accumulation (16 terms <= 1600 -> safe), double at reduce.
// ============================================================================
__global__ __launch_bounds__(256) void loss_kernel(const float4* __restrict__ zs4,
                                                   const uint4*  __restrict__ sm4,
                                                   const float4* __restrict__ gn4,
                                                   float* __restrict__ out,
                                                   unsigned nblocks) {
    __shared__ double wpart[8];
    const int t    = threadIdx.x;
    const int lane = t & 31;
    const int w    = t >> 5;
    const int b    = blockIdx.x >> 4;               // 16 blocks per batch
    const int blockBase = blockIdx.x * 1024;
    const uint32_t T = g_T[b];

    uint4  u[4];
    float4 za[4], zb[4], ga[4], gb[4];
    #pragma unroll
    for (int j = 0; j < 4; j++) {
        const int g = blockBase + j * 256 + t;
        u[j]  = sm4[g];
        za[j] = __ldcs(&zs4[2 * g]);
        zb[j] = __ldcs(&zs4[2 * g + 1]);
        ga[j] = __ldcs(&gn4[2 * g]);
        gb[j] = __ldcs(&gn4[2 * g + 1]);
    }

    float facc = 0.0f;
    #pragma unroll
    for (int j = 0; j < 4; j++) {
        float d0 = (za[j].x + ga[j].x) - (za[j].y + ga[j].y);
        float d1 = (za[j].z + ga[j].z) - (za[j].w + ga[j].w);
        float d2 = (zb[j].x + gb[j].x) - (zb[j].y + gb[j].y);
        float d3 = (zb[j].z + gb[j].z) - (zb[j].w + gb[j].w);
        #pragma unroll
        for (int c = 0; c < 4; c++) {
            float    d  = (c == 0) ? d0 : (c == 1) ? d1 : (c == 2) ? d2 : d3;
            uint32_t uu = (c == 0) ? u[j].x : (c == 1) ? u[j].y : (c == 2) ? u[j].z : u[j].w;
            bool sel;
            if (uu > T)       sel = true;
            else if (uu == T) sel = (atomicAdd(&g_eqcnt[b], 1u) < g_req[b]);  // rare
            else              sel = false;
            float cterm = __logf(1.0f + __expf(-fabsf(d)));
            float v = cterm + fmaxf(d, 0.0f) - (sel ? d : 0.0f);
            facc += fminf(v, 100.0f);
        }
    }

    double acc = (double)facc;
    #pragma unroll
    for (int off = 16; off > 0; off >>= 1)
        acc += __shfl_down_sync(0xFFFFFFFFu, acc, off);
    if (lane == 0) wpart[w] = acc;
    __syncthreads();

    if (t == 0) {
        double bsum = 0.0;
        #pragma unroll
        for (int i = 0; i < 8; i++) bsum += wpart[i];
        atomicAdd(&g_acc, bsum);
        __threadfence();
        unsigned ticket = atomicAdd(&g_done, 1u);
        if (ticket == nblocks - 1) {                 // last block: finalize + reset
            __threadfence();
            out[0] = (float)atomicAdd(&g_acc, 0.0);
            #pragma unroll 4
            for (int i = 0; i < BATCH; i++) {
                g_c2[i] = 0u; g_nc[i] = 0u; g_of[i] = 0u; g_eqcnt[i] = 0u;
            }
            g_acc = 0.0;
            __threadfence();
            g_done = 0u;
        }
    }
}

extern "C" void kernel_launch(void* const* d_in, const int* in_sizes, int n_in,
                              void* d_out, int out_size) {
    const float* scores = (const float*)d_in[0];   // [B, N, 2]
    const float* smap   = (const float*)d_in[1];   // [B, 1, H, W] == [B, N]
    const float* gumb   = (const float*)d_in[2];   // [B, N, 2]
    float* out = (float*)d_out;

    gather_kernel<<<1024, 256>>>((const uint4*)smap);
    thresh_kernel<<<BATCH, 512>>>(smap);
    loss_kernel<<<1024, 256>>>((const float4*)scores, (const uint4*)smap,
                               (const float4*)gumb, out, 1024u);
}